// round 1
// baseline (speedup 1.0000x reference)
#include <cuda_runtime.h>

// Flow-warp bilinear sampling: out[b,c,y,x] = bilerp(src[b,c], y+flow[b,0,y,x], x+flow[b,1,y,x])
// with border clamping. B=8, C=16, H=W=512.

#define B_ 8
#define C_ 16
#define H_ 512
#define W_ 512
#define HW_ (H_ * W_)
#define CHW_ (C_ * HW_)

__global__ void __launch_bounds__(256) warp_bilinear_kernel(
    const float* __restrict__ src,
    const float* __restrict__ flow,
    float* __restrict__ out)
{
    int idx = blockIdx.x * blockDim.x + threadIdx.x;   // over B*H*W = 2,097,152
    if (idx >= B_ * HW_) return;

    int x = idx & (W_ - 1);
    int y = (idx >> 9) & (H_ - 1);
    int b = idx >> 18;

    // flow plane 0 = dy, plane 1 = dx
    const float fy = __ldg(flow + (size_t)b * 2 * HW_ + (size_t)y * W_ + x);
    const float fx = __ldg(flow + (size_t)b * 2 * HW_ + HW_ + (size_t)y * W_ + x);

    // normalize->unnormalize cancels exactly; border clamp on source coords
    float py = fminf(fmaxf((float)y + fy, 0.0f), (float)(H_ - 1));
    float px = fminf(fmaxf((float)x + fx, 0.0f), (float)(W_ - 1));

    float y0f = floorf(py);
    float x0f = floorf(px);
    float wy = py - y0f;
    float wx = px - x0f;

    int y0 = (int)y0f;
    int x0 = (int)x0f;
    int y1 = min(y0 + 1, H_ - 1);
    int x1 = min(x0 + 1, W_ - 1);

    int o00 = y0 * W_ + x0;
    int o01 = y0 * W_ + x1;
    int o10 = y1 * W_ + x0;
    int o11 = y1 * W_ + x1;

    const float* __restrict__ sb = src + (size_t)b * CHW_;
    float* __restrict__ ob = out + (size_t)b * CHW_ + (size_t)y * W_ + x;

#pragma unroll
    for (int c = 0; c < C_; ++c) {
        const float* __restrict__ sc = sb + (size_t)c * HW_;
        float v00 = __ldg(sc + o00);
        float v01 = __ldg(sc + o01);
        float v10 = __ldg(sc + o10);
        float v11 = __ldg(sc + o11);
        float top = fmaf(wx, v01 - v00, v00);
        float bot = fmaf(wx, v11 - v10, v10);
        ob[(size_t)c * HW_] = fmaf(wy, bot - top, top);
    }
}

extern "C" void kernel_launch(void* const* d_in, const int* in_sizes, int n_in,
                              void* d_out, int out_size)
{
    const float* src  = (const float*)d_in[0];
    const float* flow = (const float*)d_in[1];
    float* out        = (float*)d_out;

    const int total = B_ * HW_;
    const int threads = 256;
    const int blocks = (total + threads - 1) / threads;
    warp_bilinear_kernel<<<blocks, threads>>>(src, flow, out);
}